// round 6
// baseline (speedup 1.0000x reference)
#include <cuda_runtime.h>
#include <math.h>

// Problem constants (fixed by reference setup_inputs)
#define BD     8
#define LD     1024
#define SD     1000
#define DMODEL 1024
#define DLLM   4096
#define NH     8
#define EDIM   128
#define INNER  1024   // NH*EDIM

#define ATTN_SCALE 0.088388347648318447f  // 1/sqrt(128)

typedef unsigned long long ull;

// Scratch (device globals: no allocation allowed)
__device__ float g_Q[(size_t)BD * LD * INNER];    // (B*L, INNER)
__device__ float g_K[(size_t)SD * INNER];         // (S, INNER)
__device__ float g_V[(size_t)SD * INNER];         // (S, INNER)
__device__ float g_ctx[(size_t)BD * LD * INNER];  // (B*L, INNER)

// ---- packed f32x2 helpers (Blackwell sm_100+) ------------------------------
__device__ __forceinline__ ull pack2(float x, float y) {
    ull r; asm("mov.b64 %0, {%1,%2};" : "=l"(r) : "f"(x), "f"(y)); return r;
}
__device__ __forceinline__ float2 unpack2(ull v) {
    float2 r; asm("mov.b64 {%0,%1}, %2;" : "=f"(r.x), "=f"(r.y) : "l"(v)); return r;
}
__device__ __forceinline__ void fma2(ull& c, ull a, ull b) {
    asm("fma.rn.f32x2 %0, %1, %2, %0;" : "+l"(c) : "l"(a), "l"(b));
}
__device__ __forceinline__ ull mul2(ull a, ull b) {
    ull r; asm("mul.rn.f32x2 %0, %1, %2;" : "=l"(r) : "l"(a), "l"(b)); return r;
}

// ---- Generic SGEMM + bias body: C[row0.., col0..] tile ---------------------
// 128x128 block tile, BK=8, 256 threads, 8x8 per thread via f32x2.
// Double-buffered smem, one barrier per K-step.
// A tile stored DUPLICATED ((a,a) pairs): one LDS.64 yields a packed f32x2
// broadcast operand. Callers pin 2 CTAs/SM via __launch_bounds__ so
// co-resident CTAs cover each other's barrier / LDG-wait gaps.
#define AS_STRIDE 264  // 2*128 duplicated + 8 pad (keeps 8B alignment)

__device__ __forceinline__ void sgemm_body(
    const float* __restrict__ A, const float* __restrict__ W,
    const float* __restrict__ bias, float* __restrict__ C,
    int M, int N, int K, int row0, int col0)
{
    __shared__ float As[2][8][AS_STRIDE];  // [buf][k][2*row(+dup)]
    __shared__ float Bs[2][8][128];        // [buf][k][col]

    const int tid  = threadIdx.x;

    const int arow = tid >> 1;          // 0..127
    const int acol = (tid & 1) * 4;     // 0 or 4
    const int brow = tid >> 5;          // 0..7
    const int bcol = (tid & 31) * 4;    // 0..124
    const int tm   = (tid >> 4) * 8;    // row frag base
    const int tx   = tid & 15;          // col group

    ull c2[8][4];
    #pragma unroll
    for (int i = 0; i < 8; i++)
        #pragma unroll
        for (int j = 0; j < 4; j++) c2[i][j] = 0ull;

    const bool aok = (row0 + arow) < M;
    const float* Ap = A + (size_t)(row0 + arow) * K + acol;
    const float* Wp = W + (size_t)brow * N + col0 + bcol;

    // ---- prologue: load tile 0 into buffer 0 ----
    {
        float4 av = make_float4(0.f, 0.f, 0.f, 0.f);
        if (aok) av = *(const float4*)(Ap);
        *(float2*)&As[0][acol + 0][2 * arow] = make_float2(av.x, av.x);
        *(float2*)&As[0][acol + 1][2 * arow] = make_float2(av.y, av.y);
        *(float2*)&As[0][acol + 2][2 * arow] = make_float2(av.z, av.z);
        *(float2*)&As[0][acol + 3][2 * arow] = make_float2(av.w, av.w);
        *(float4*)&Bs[0][brow][bcol] = *(const float4*)(Wp);
    }
    __syncthreads();

    int cur = 0;
    for (int k0 = 8; k0 <= K; k0 += 8) {
        // ---- issue next-tile global loads early (overlap with compute) ----
        float4 avn = make_float4(0.f, 0.f, 0.f, 0.f), bvn;
        const bool more = (k0 < K);
        if (more) {
            if (aok) avn = *(const float4*)(Ap + k0);
            bvn = *(const float4*)(Wp + (size_t)k0 * N);
        }

        // ---- compute on current buffer ----
        #pragma unroll
        for (int kk = 0; kk < 8; kk++) {
            ull a2[8];
            #pragma unroll
            for (int i = 0; i < 8; i++)
                a2[i] = *(const ull*)&As[cur][kk][2 * (tm + i)];
            ull b2[4];
            b2[0] = *(const ull*)&Bs[cur][kk][4 * tx];
            b2[1] = *(const ull*)&Bs[cur][kk][4 * tx + 2];
            b2[2] = *(const ull*)&Bs[cur][kk][64 + 4 * tx];
            b2[3] = *(const ull*)&Bs[cur][kk][64 + 4 * tx + 2];
            #pragma unroll
            for (int i = 0; i < 8; i++) {
                fma2(c2[i][0], a2[i], b2[0]);
                fma2(c2[i][1], a2[i], b2[1]);
                fma2(c2[i][2], a2[i], b2[2]);
                fma2(c2[i][3], a2[i], b2[3]);
            }
        }

        // ---- store next tile into the other buffer, single barrier ----
        if (more) {
            int nxt = cur ^ 1;
            *(float2*)&As[nxt][acol + 0][2 * arow] = make_float2(avn.x, avn.x);
            *(float2*)&As[nxt][acol + 1][2 * arow] = make_float2(avn.y, avn.y);
            *(float2*)&As[nxt][acol + 2][2 * arow] = make_float2(avn.z, avn.z);
            *(float2*)&As[nxt][acol + 3][2 * arow] = make_float2(avn.w, avn.w);
            *(float4*)&Bs[nxt][brow][bcol] = bvn;
            __syncthreads();
            cur = nxt;
        }
    }

    const int cA = col0 + 4 * tx;
    const int cB = cA + 64;
    float4 bA = *(const float4*)(bias + cA);
    float4 bB = *(const float4*)(bias + cB);
    #pragma unroll
    for (int i = 0; i < 8; i++) {
        int r = row0 + tm + i;
        if (r < M) {
            float2 p0 = unpack2(c2[i][0]), p1 = unpack2(c2[i][1]);
            float2 p2 = unpack2(c2[i][2]), p3 = unpack2(c2[i][3]);
            float4 oA = make_float4(p0.x + bA.x, p0.y + bA.y, p1.x + bA.z, p1.y + bA.w);
            float4 oB = make_float4(p2.x + bB.x, p2.y + bB.y, p3.x + bB.z, p3.y + bB.w);
            *(float4*)(C + (size_t)r * N + cA) = oA;
            *(float4*)(C + (size_t)r * N + cB) = oB;
        }
    }
}

// Plain GEMM kernel (used for the big output projection).
__global__ __launch_bounds__(256, 2) void sgemm_bias(
    const float* __restrict__ A, const float* __restrict__ W,
    const float* __restrict__ bias, float* __restrict__ C,
    int M, int N, int K)
{
    sgemm_body(A, W, bias, C, M, N, K, blockIdx.y * 128, blockIdx.x * 128);
}

// Fused Q+K+V projection: one launch, grid (8, 80), no empty CTAs.
//   y in [0,64)  -> Q tile row y      (A=te, K=1024, M=8192)
//   y in [64,72) -> K tile row y-64   (A=se, K=4096, M=1000)
//   y in [72,80) -> V tile row y-72   (A=ve, K=4096, M=1000)
// Removes the 57%-idle standalone K/V launch; long K/V CTAs start in wave 1
// and overlap the Q tail (work-steal scheduler).
__global__ __launch_bounds__(256, 2) void proj_qkv(
    const float* __restrict__ te,
    const float* __restrict__ se, const float* __restrict__ ve,
    const float* __restrict__ Wq, const float* __restrict__ bq,
    const float* __restrict__ Wk, const float* __restrict__ bk,
    const float* __restrict__ Wv, const float* __restrict__ bv,
    float* __restrict__ Qp, float* __restrict__ Kp, float* __restrict__ Vp)
{
    const int y = blockIdx.y;
    const float *A, *W, *bia;
    float* C;
    int M, K, row0;
    if (y < 64) {
        A = te; W = Wq; bia = bq; C = Qp;
        M = BD * LD; K = DMODEL; row0 = y * 128;
    } else if (y < 72) {
        A = se; W = Wk; bia = bk; C = Kp;
        M = SD; K = DLLM; row0 = (y - 64) * 128;
    } else {
        A = ve; W = Wv; bia = bv; C = Vp;
        M = SD; K = DLLM; row0 = (y - 72) * 128;
    }
    sgemm_body(A, W, bia, C, M, INNER, K, row0, blockIdx.x * 128);
}

// ---- Flash attention (fp32, online softmax) --------------------------------
// Block: one (b, h, 64-row L tile). 256 threads. S tiled by 64.
// 84.5 KB dynamic smem -> 2 CTAs/SM by smem; pin occupancy 2 via launch bounds.
#define AQ_STRIDE 132
#define KT_STRIDE 66
#define PS_STRIDE 66
#define KV_FLOATS 8448  // max(128*KT_STRIDE=8448, 64*128=8192)
#define ATTN_SMEM ((64 * AQ_STRIDE + KV_FLOATS + 64 * PS_STRIDE) * 4)

__global__ __launch_bounds__(256, 2) void attn_kernel()
{
    extern __shared__ float sm[];
    float* Qs = sm;                         // [64][AQ_STRIDE]
    float* KV = sm + 64 * AQ_STRIDE;        // K^T [128][KT_STRIDE] or V [64][128]
    float* Ps = KV + KV_FLOATS;             // [64][PS_STRIDE]

    const int tid = threadIdx.x;
    const int l0  = blockIdx.x * 64;
    const int h   = blockIdx.y;
    const int b   = blockIdx.z;

    // Load Q tile (64 x 128)
    const float* Qg = g_Q + ((size_t)(b * LD + l0)) * INNER + h * EDIM;
    #pragma unroll
    for (int i = 0; i < 8; i++) {
        int f = tid + i * 256;
        int r = f >> 5;
        int c = (f & 31) * 4;
        float4 v = *(const float4*)(Qg + (size_t)r * INNER + c);
        Qs[r * AQ_STRIDE + c + 0] = v.x;
        Qs[r * AQ_STRIDE + c + 1] = v.y;
        Qs[r * AQ_STRIDE + c + 2] = v.z;
        Qs[r * AQ_STRIDE + c + 3] = v.w;
    }

    const int rowb  = (tid >> 4) * 4;   // 4 L-rows per thread
    const int colb  = (tid & 15) * 4;   // 4 S-cols per thread (P tile)
    const int colb2 = (tid & 15) * 8;   // 8 E-cols per thread (O tile)

    float m[4], lsum[4];
    ull o2[4][4];
    #pragma unroll
    for (int i = 0; i < 4; i++) {
        m[i] = -INFINITY;
        lsum[i] = 0.f;
        #pragma unroll
        for (int j = 0; j < 4; j++) o2[i][j] = 0ull;
    }
    __syncthreads();

    for (int s0 = 0; s0 < SD; s0 += 64) {
        // ---- load K tile transposed: KV[e][s] ----
        const float* Kg = g_K + (size_t)s0 * INNER + h * EDIM;
        #pragma unroll
        for (int i = 0; i < 8; i++) {
            int f  = tid + i * 256;
            int sr = f >> 5;
            int c  = (f & 31) * 4;
            float4 v = make_float4(0.f, 0.f, 0.f, 0.f);
            if (s0 + sr < SD) v = *(const float4*)(Kg + (size_t)sr * INNER + c);
            KV[(c + 0) * KT_STRIDE + sr] = v.x;
            KV[(c + 1) * KT_STRIDE + sr] = v.y;
            KV[(c + 2) * KT_STRIDE + sr] = v.z;
            KV[(c + 3) * KT_STRIDE + sr] = v.w;
        }
        __syncthreads();

        // ---- P = Q @ K^T (64x64), frag 4x4 per thread ----
        ull pc2[4][2];
        #pragma unroll
        for (int i = 0; i < 4; i++) { pc2[i][0] = 0ull; pc2[i][1] = 0ull; }
        #pragma unroll 4
        for (int e = 0; e < EDIM; e++) {
            ull b0 = *(const ull*)&KV[e * KT_STRIDE + colb];
            ull b1 = *(const ull*)&KV[e * KT_STRIDE + colb + 2];
            #pragma unroll
            for (int i = 0; i < 4; i++) {
                float a = Qs[(rowb + i) * AQ_STRIDE + e];
                ull a2 = pack2(a, a);
                fma2(pc2[i][0], a2, b0);
                fma2(pc2[i][1], a2, b1);
            }
        }

        // ---- online softmax update ----
        #pragma unroll
        for (int i = 0; i < 4; i++) {
            float2 q0 = unpack2(pc2[i][0]);
            float2 q1 = unpack2(pc2[i][1]);
            float sc[4] = {q0.x, q0.y, q1.x, q1.y};
            #pragma unroll
            for (int j = 0; j < 4; j++) {
                sc[j] *= ATTN_SCALE;
                if (s0 + colb + j >= SD) sc[j] = -INFINITY;
            }
            float mx = fmaxf(fmaxf(sc[0], sc[1]), fmaxf(sc[2], sc[3]));
            mx = fmaxf(mx, __shfl_xor_sync(0xffffffffu, mx, 8));
            mx = fmaxf(mx, __shfl_xor_sync(0xffffffffu, mx, 4));
            mx = fmaxf(mx, __shfl_xor_sync(0xffffffffu, mx, 2));
            mx = fmaxf(mx, __shfl_xor_sync(0xffffffffu, mx, 1));
            float mn = fmaxf(m[i], mx);
            float al = __expf(m[i] - mn);
            m[i] = mn;
            float rs = 0.f;
            #pragma unroll
            for (int j = 0; j < 4; j++) {
                float p = __expf(sc[j] - mn);
                Ps[(rowb + i) * PS_STRIDE + colb + j] = p;
                rs += p;
            }
            rs += __shfl_xor_sync(0xffffffffu, rs, 8);
            rs += __shfl_xor_sync(0xffffffffu, rs, 4);
            rs += __shfl_xor_sync(0xffffffffu, rs, 2);
            rs += __shfl_xor_sync(0xffffffffu, rs, 1);
            lsum[i] = lsum[i] * al + rs;
            ull alp = pack2(al, al);
            #pragma unroll
            for (int j = 0; j < 4; j++) o2[i][j] = mul2(o2[i][j], alp);
        }
        __syncthreads();  // K reads + Ps writes done

        // ---- load V tile row-major: KV[s][e] ----
        const float* Vg = g_V + (size_t)s0 * INNER + h * EDIM;
        #pragma unroll
        for (int i = 0; i < 8; i++) {
            int f  = tid + i * 256;
            int sr = f >> 5;
            int c  = (f & 31) * 4;
            float4 v = make_float4(0.f, 0.f, 0.f, 0.f);
            if (s0 + sr < SD) v = *(const float4*)(Vg + (size_t)sr * INNER + c);
            *(float4*)&KV[sr * 128 + c] = v;
        }
        __syncthreads();

        // ---- O += P~ @ V (64x128), frag 4x8 per thread ----
        #pragma unroll 2
        for (int s = 0; s < 64; s++) {
            ull b2[4];
            b2[0] = *(const ull*)&KV[s * 128 + colb2];
            b2[1] = *(const ull*)&KV[s * 128 + colb2 + 2];
            b2[2] = *(const ull*)&KV[s * 128 + colb2 + 4];
            b2[3] = *(const ull*)&KV[s * 128 + colb2 + 6];
            #pragma unroll
            for (int i = 0; i < 4; i++) {
                float a = Ps[(rowb + i) * PS_STRIDE + s];
                ull a2 = pack2(a, a);
                fma2(o2[i][0], a2, b2[0]);
                fma2(o2[i][1], a2, b2[1]);
                fma2(o2[i][2], a2, b2[2]);
                fma2(o2[i][3], a2, b2[3]);
            }
        }
        __syncthreads();  // V reads done before next K overwrite
    }

    // ---- epilogue: O / l -> ctx ----
    float* Cg = g_ctx + ((size_t)(b * LD + l0 + rowb)) * INNER + h * EDIM + colb2;
    #pragma unroll
    for (int i = 0; i < 4; i++) {
        float inv = 1.f / lsum[i];
        float2 p0 = unpack2(o2[i][0]), p1 = unpack2(o2[i][1]);
        float2 p2 = unpack2(o2[i][2]), p3 = unpack2(o2[i][3]);
        float4 oA = make_float4(p0.x * inv, p0.y * inv, p1.x * inv, p1.y * inv);
        float4 oB = make_float4(p2.x * inv, p2.y * inv, p3.x * inv, p3.y * inv);
        *(float4*)(Cg + (size_t)i * INNER)     = oA;
        *(float4*)(Cg + (size_t)i * INNER + 4) = oB;
    }
}

// ---- launch ---------------------------------------------------------------
extern "C" void kernel_launch(void* const* d_in, const int* in_sizes, int n_in,
                              void* d_out, int out_size)
{
    (void)in_sizes; (void)n_in; (void)out_size;
    const float* te = (const float*)d_in[0];
    const float* se = (const float*)d_in[1];
    const float* ve = (const float*)d_in[2];
    const float* Wq = (const float*)d_in[3];
    const float* bq = (const float*)d_in[4];
    const float* Wk = (const float*)d_in[5];
    const float* bk = (const float*)d_in[6];
    const float* Wv = (const float*)d_in[7];
    const float* bv = (const float*)d_in[8];
    const float* Wo = (const float*)d_in[9];
    const float* bo = (const float*)d_in[10];
    float* out = (float*)d_out;

    float *Qp, *Kp, *Vp, *Cp;
    cudaGetSymbolAddress((void**)&Qp, g_Q);
    cudaGetSymbolAddress((void**)&Kp, g_K);
    cudaGetSymbolAddress((void**)&Vp, g_V);
    cudaGetSymbolAddress((void**)&Cp, g_ctx);

    cudaFuncSetAttribute(attn_kernel,
                         cudaFuncAttributeMaxDynamicSharedMemorySize, ATTN_SMEM);

    dim3 blk(256);
    // 1) Q,K,V projections fused into one launch (grid 8 x 80, no empties)
    proj_qkv<<<dim3(INNER / 128, 80), blk>>>(
        te, se, ve, Wq, bq, Wk, bk, Wv, bv, Qp, Kp, Vp);
    // 2) attention -> ctx
    attn_kernel<<<dim3(LD / 64, NH, BD), blk, ATTN_SMEM>>>();
    // 3) out = ctx @ Wo + bo (8192 x 4096, K=1024)
    sgemm_bias<<<dim3(DLLM / 128, (BD * LD) / 128), blk>>>(Cp, Wo, bo, out, BD * LD, DLLM, INNER);
}